// round 1
// baseline (speedup 1.0000x reference)
#include <cuda_runtime.h>

// LocalitySelfAttention: B=8, N=2304 (48x48), C=512, H=8, D=64.
// Pipeline: [qkv GEMM + scatter] -> [fused flash attention w/ locality bias] -> [proj GEMM + bias]
// All fp32 this round (correctness baseline; tensor-core rounds follow).

constexpr int BB = 8;
constexpr int NN = 2304;
constexpr int CC = 512;
constexpr int HH = 8;
constexpr int DD = 64;
constexpr int GG = 48;
constexpr int M_TOT = BB * NN;     // 18432
constexpr int QKV_OUT = 3 * CC;    // 1536

// Scratch (device globals; no runtime allocation allowed)
__device__ float g_q[(size_t)BB * HH * NN * DD];
__device__ float g_k[(size_t)BB * HH * NN * DD];
__device__ float g_v[(size_t)BB * HH * NN * DD];
__device__ float g_att[(size_t)BB * NN * CC];

// ---------------------------------------------------------------------------
// Kernel 1: Y = X @ Wqkv^T with scatter epilogue into q/k/v [b][h][n][d]
// X: (18432, 512) row-major, W: (1536, 512) row-major (out_features, in_features)
// Tiles: 128x128x8, 256 threads, 8x8 per thread.
// ---------------------------------------------------------------------------
__global__ __launch_bounds__(256, 2)
void qkv_gemm_kernel(const float* __restrict__ A, const float* __restrict__ W) {
    __shared__ float As[8][128];
    __shared__ float Bs[8][128];
    const int tid = threadIdx.x;
    const int tx = tid & 15;
    const int ty = tid >> 4;
    const int lrow = tid >> 1;          // 0..127
    const int lcol = (tid & 1) << 2;    // 0 or 4
    const int bm = blockIdx.x * 128;
    const int bn = blockIdx.y * 128;

    const float* Ap = A + (size_t)(bm + lrow) * CC + lcol;
    const float* Bp = W + (size_t)(bn + lrow) * CC + lcol;

    float acc[8][8];
#pragma unroll
    for (int i = 0; i < 8; i++)
#pragma unroll
        for (int j = 0; j < 8; j++) acc[i][j] = 0.0f;

    for (int k0 = 0; k0 < CC; k0 += 8) {
        float4 av = *(const float4*)(Ap + k0);
        float4 bv = *(const float4*)(Bp + k0);
        __syncthreads();
        As[lcol + 0][lrow] = av.x; As[lcol + 1][lrow] = av.y;
        As[lcol + 2][lrow] = av.z; As[lcol + 3][lrow] = av.w;
        Bs[lcol + 0][lrow] = bv.x; Bs[lcol + 1][lrow] = bv.y;
        Bs[lcol + 2][lrow] = bv.z; Bs[lcol + 3][lrow] = bv.w;
        __syncthreads();
#pragma unroll
        for (int kk = 0; kk < 8; kk++) {
            float ar[8], br[8];
            *(float4*)&ar[0] = *(const float4*)&As[kk][ty * 8];
            *(float4*)&ar[4] = *(const float4*)&As[kk][ty * 8 + 4];
            *(float4*)&br[0] = *(const float4*)&Bs[kk][tx * 8];
            *(float4*)&br[4] = *(const float4*)&Bs[kk][tx * 8 + 4];
#pragma unroll
            for (int i = 0; i < 8; i++)
#pragma unroll
                for (int j = 0; j < 8; j++)
                    acc[i][j] = fmaf(ar[i], br[j], acc[i][j]);
        }
    }

    // Scatter epilogue: o -> (part, h, d); m -> (b, n)
#pragma unroll
    for (int i = 0; i < 8; i++) {
        const int m = bm + ty * 8 + i;
        const int b = m / NN;
        const int n = m - b * NN;
#pragma unroll
        for (int j = 0; j < 8; j++) {
            const int o = bn + tx * 8 + j;
            const int part = o >> 9;
            const int h = (o >> 6) & 7;
            const int d = o & 63;
            float* dst = (part == 0) ? g_q : ((part == 1) ? g_k : g_v);
            dst[(((size_t)b * HH + h) * NN + n) * DD + d] = acc[i][j];
        }
    }
}

// ---------------------------------------------------------------------------
// Kernel 2: fused flash attention with locality bias.
// One block = one (b,h) x 64-query tile. 256 threads = 16x16, 4x4 per thread.
// smem (dynamic, padded stride 68): Qs[d][q], KPs[d][k] (reused as P[k][q]), Vs[k][d]
// ---------------------------------------------------------------------------
constexpr int FL_STRIDE = 68;
constexpr int FL_SMEM_BYTES = 3 * 64 * FL_STRIDE * (int)sizeof(float);  // 52224

__global__ __launch_bounds__(256, 2)
void flash_kernel(const float* __restrict__ temp, const float* __restrict__ lw) {
    extern __shared__ float sm[];
    float (*Qs)[FL_STRIDE]  = (float(*)[FL_STRIDE])(sm);
    float (*KPs)[FL_STRIDE] = (float(*)[FL_STRIDE])(sm + 64 * FL_STRIDE);
    float (*Vs)[FL_STRIDE]  = (float(*)[FL_STRIDE])(sm + 2 * 64 * FL_STRIDE);

    const int tid = threadIdx.x;
    const int tx = tid & 15;
    const int ty = tid >> 4;
    const int qt = blockIdx.x;          // 0..35
    const int bh = blockIdx.y;          // 0..63
    const int h  = bh & 7;
    const int b  = bh >> 3;
    const size_t base = (size_t)bh * NN * DD;
    const float* Qg = g_q + base;
    const float* Kg = g_k + base;
    const float* Vg = g_v + base;

    const float scale = __expf(temp[h]);
    // loc(q,k) = -((dy^2+dx^2)) / (2 * 47^2); weight folded in
    const float wb = lw[h] * (1.0f / 4418.0f);

    const int q0 = qt * 64;
    const int lrow = tid >> 2;          // 0..63
    const int lc = (tid & 3) << 4;      // 0,16,32,48

    // Load Q tile transposed: Qs[d][q]
#pragma unroll
    for (int u = 0; u < 4; u++) {
        float4 v = *(const float4*)(Qg + (size_t)(q0 + lrow) * DD + lc + u * 4);
        Qs[lc + u * 4 + 0][lrow] = v.x;
        Qs[lc + u * 4 + 1][lrow] = v.y;
        Qs[lc + u * 4 + 2][lrow] = v.z;
        Qs[lc + u * 4 + 3][lrow] = v.w;
    }

    float o_acc[4][4];
    float mrow[4], lsum[4];
#pragma unroll
    for (int r = 0; r < 4; r++) {
        mrow[r] = -1e30f;
        lsum[r] = 0.0f;
#pragma unroll
        for (int c = 0; c < 4; c++) o_acc[r][c] = 0.0f;
    }

    int qy[4], qx[4];
#pragma unroll
    for (int r = 0; r < 4; r++) {
        const int q = q0 + ty * 4 + r;
        qy[r] = q / GG;
        qx[r] = q - qy[r] * GG;
    }

    for (int kt = 0; kt < NN / 64; kt++) {
        __syncthreads();  // prior O-accumulate reads of KPs/Vs complete
        const int k0 = kt * 64;
        // K transposed into KPs[d][k]; V direct into Vs[k][d]
#pragma unroll
        for (int u = 0; u < 4; u++) {
            float4 kv = *(const float4*)(Kg + (size_t)(k0 + lrow) * DD + lc + u * 4);
            KPs[lc + u * 4 + 0][lrow] = kv.x;
            KPs[lc + u * 4 + 1][lrow] = kv.y;
            KPs[lc + u * 4 + 2][lrow] = kv.z;
            KPs[lc + u * 4 + 3][lrow] = kv.w;
            float4 vv = *(const float4*)(Vg + (size_t)(k0 + lrow) * DD + lc + u * 4);
            *(float4*)&Vs[lrow][lc + u * 4] = vv;
        }
        __syncthreads();

        // S = Q K^T  (4x4 per thread)
        float s[4][4];
#pragma unroll
        for (int r = 0; r < 4; r++)
#pragma unroll
            for (int c = 0; c < 4; c++) s[r][c] = 0.0f;

#pragma unroll 8
        for (int kk = 0; kk < 64; kk++) {
            float4 qv = *(const float4*)&Qs[kk][ty * 4];
            float4 kvv = *(const float4*)&KPs[kk][tx * 4];
            const float qa[4] = {qv.x, qv.y, qv.z, qv.w};
            const float ka[4] = {kvv.x, kvv.y, kvv.z, kvv.w};
#pragma unroll
            for (int r = 0; r < 4; r++)
#pragma unroll
                for (int c = 0; c < 4; c++)
                    s[r][c] = fmaf(qa[r], ka[c], s[r][c]);
        }

        // scale + locality bias
        float kyf[4], kxf[4];
        const int kb = k0 + tx * 4;
#pragma unroll
        for (int c = 0; c < 4; c++) {
            const int k = kb + c;
            const int kyi = k / GG;
            kyf[c] = (float)kyi;
            kxf[c] = (float)(k - kyi * GG);
        }
#pragma unroll
        for (int r = 0; r < 4; r++) {
            const float qyf = (float)qy[r], qxf = (float)qx[r];
#pragma unroll
            for (int c = 0; c < 4; c++) {
                const float dy = qyf - kyf[c];
                const float dx = qxf - kxf[c];
                s[r][c] = s[r][c] * scale - wb * (dy * dy + dx * dx);
            }
            // online softmax update (row-group = 16 lanes sharing ty)
            float mt = fmaxf(fmaxf(s[r][0], s[r][1]), fmaxf(s[r][2], s[r][3]));
            mt = fmaxf(mt, __shfl_xor_sync(0xffffffffu, mt, 1, 16));
            mt = fmaxf(mt, __shfl_xor_sync(0xffffffffu, mt, 2, 16));
            mt = fmaxf(mt, __shfl_xor_sync(0xffffffffu, mt, 4, 16));
            mt = fmaxf(mt, __shfl_xor_sync(0xffffffffu, mt, 8, 16));
            const float mn = fmaxf(mrow[r], mt);
            const float fac = __expf(mrow[r] - mn);
            mrow[r] = mn;
            lsum[r] *= fac;
#pragma unroll
            for (int c = 0; c < 4; c++) o_acc[r][c] *= fac;
            float ps = 0.0f;
#pragma unroll
            for (int c = 0; c < 4; c++) {
                const float p = __expf(s[r][c] - mn);
                s[r][c] = p;
                ps += p;
            }
            lsum[r] += ps;
        }

        __syncthreads();  // all S-reads of KPs (K data) done
        // store P transposed: KPs[k][q]
#pragma unroll
        for (int c = 0; c < 4; c++) {
            *(float4*)&KPs[tx * 4 + c][ty * 4] =
                make_float4(s[0][c], s[1][c], s[2][c], s[3][c]);
        }
        __syncthreads();

        // O += P V
#pragma unroll 8
        for (int kk = 0; kk < 64; kk++) {
            float4 pv = *(const float4*)&KPs[kk][ty * 4];
            float4 vv = *(const float4*)&Vs[kk][tx * 4];
            const float pa[4] = {pv.x, pv.y, pv.z, pv.w};
            const float va[4] = {vv.x, vv.y, vv.z, vv.w};
#pragma unroll
            for (int r = 0; r < 4; r++)
#pragma unroll
                for (int c = 0; c < 4; c++)
                    o_acc[r][c] = fmaf(pa[r], va[c], o_acc[r][c]);
        }
    }

    // finalize: divide by full row sum, write (B, N, C) layout
#pragma unroll
    for (int r = 0; r < 4; r++) {
        float lt = lsum[r];
        lt += __shfl_xor_sync(0xffffffffu, lt, 1, 16);
        lt += __shfl_xor_sync(0xffffffffu, lt, 2, 16);
        lt += __shfl_xor_sync(0xffffffffu, lt, 4, 16);
        lt += __shfl_xor_sync(0xffffffffu, lt, 8, 16);
        const float inv = 1.0f / lt;
        const int q = q0 + ty * 4 + r;
        float* dst = g_att + ((size_t)(b * NN + q)) * CC + h * DD + tx * 4;
        *(float4*)dst = make_float4(o_acc[r][0] * inv, o_acc[r][1] * inv,
                                    o_acc[r][2] * inv, o_acc[r][3] * inv);
    }
}

// ---------------------------------------------------------------------------
// Kernel 3: out = g_att @ Wproj^T + bias. Same SGEMM skeleton.
// ---------------------------------------------------------------------------
__global__ __launch_bounds__(256, 2)
void proj_gemm_kernel(const float* __restrict__ W, const float* __restrict__ bias,
                      float* __restrict__ out) {
    __shared__ float As[8][128];
    __shared__ float Bs[8][128];
    const int tid = threadIdx.x;
    const int tx = tid & 15;
    const int ty = tid >> 4;
    const int lrow = tid >> 1;
    const int lcol = (tid & 1) << 2;
    const int bm = blockIdx.x * 128;
    const int bn = blockIdx.y * 128;

    const float* Ap = g_att + (size_t)(bm + lrow) * CC + lcol;
    const float* Bp = W + (size_t)(bn + lrow) * CC + lcol;

    float acc[8][8];
#pragma unroll
    for (int i = 0; i < 8; i++)
#pragma unroll
        for (int j = 0; j < 8; j++) acc[i][j] = 0.0f;

    for (int k0 = 0; k0 < CC; k0 += 8) {
        float4 av = *(const float4*)(Ap + k0);
        float4 bv = *(const float4*)(Bp + k0);
        __syncthreads();
        As[lcol + 0][lrow] = av.x; As[lcol + 1][lrow] = av.y;
        As[lcol + 2][lrow] = av.z; As[lcol + 3][lrow] = av.w;
        Bs[lcol + 0][lrow] = bv.x; Bs[lcol + 1][lrow] = bv.y;
        Bs[lcol + 2][lrow] = bv.z; Bs[lcol + 3][lrow] = bv.w;
        __syncthreads();
#pragma unroll
        for (int kk = 0; kk < 8; kk++) {
            float ar[8], br[8];
            *(float4*)&ar[0] = *(const float4*)&As[kk][ty * 8];
            *(float4*)&ar[4] = *(const float4*)&As[kk][ty * 8 + 4];
            *(float4*)&br[0] = *(const float4*)&Bs[kk][tx * 8];
            *(float4*)&br[4] = *(const float4*)&Bs[kk][tx * 8 + 4];
#pragma unroll
            for (int i = 0; i < 8; i++)
#pragma unroll
                for (int j = 0; j < 8; j++)
                    acc[i][j] = fmaf(ar[i], br[j], acc[i][j]);
        }
    }

#pragma unroll
    for (int i = 0; i < 8; i++) {
        const int m = bm + ty * 8 + i;
        float* orow = out + (size_t)m * CC + bn + tx * 8;
#pragma unroll
        for (int j = 0; j < 8; j++)
            orow[j] = acc[i][j] + bias[bn + tx * 8 + j];
    }
}

// ---------------------------------------------------------------------------
extern "C" void kernel_launch(void* const* d_in, const int* in_sizes, int n_in,
                              void* d_out, int out_size) {
    const float* x      = (const float*)d_in[0];  // (B, N, C)
    const float* qkv_w  = (const float*)d_in[1];  // (3C, C)
    const float* proj_w = (const float*)d_in[2];  // (C, C)
    const float* proj_b = (const float*)d_in[3];  // (C,)
    const float* temp   = (const float*)d_in[4];  // (H,1,1)
    const float* lw     = (const float*)d_in[5];  // (H,)
    float* out = (float*)d_out;

    qkv_gemm_kernel<<<dim3(M_TOT / 128, QKV_OUT / 128), 256>>>(x, qkv_w);

    cudaFuncSetAttribute(flash_kernel, cudaFuncAttributeMaxDynamicSharedMemorySize,
                         FL_SMEM_BYTES);
    flash_kernel<<<dim3(NN / 64, BB * HH), 256, FL_SMEM_BYTES>>>(temp, lw);

    proj_gemm_kernel<<<dim3(M_TOT / 128, CC / 128), 256>>>(proj_w, proj_b, out);
}

// round 3
// speedup vs baseline: 2.1798x; 2.1798x over previous
#include <cuda_runtime.h>
#include <cuda_bf16.h>
#include <stdint.h>

// LocalitySelfAttention: B=8, N=2304 (48x48), C=512, H=8, D=64.
// All matmuls on tensor pipe: mma.sync.m16n8k16.bf16 with hi/lo error-split
// (3 MMAs per logical product -> ~fp32-class accuracy, ~1e-5 rel err).

constexpr int BB = 8;
constexpr int NN = 2304;
constexpr int CC = 512;
constexpr int HH = 8;
constexpr int DD = 64;
constexpr int GG = 48;
constexpr int M_TOT = BB * NN;     // 18432

__device__ float g_q[(size_t)BB * HH * NN * DD];
__device__ float g_k[(size_t)BB * HH * NN * DD];
__device__ float g_v[(size_t)BB * HH * NN * DD];
__device__ float g_att[(size_t)BB * NN * CC];

__device__ __forceinline__ uint32_t pack2(__nv_bfloat16 a, __nv_bfloat16 b) {
    __nv_bfloat162 t; t.x = a; t.y = b;
    return *reinterpret_cast<uint32_t*>(&t);
}
__device__ __forceinline__ void split2(float x, __nv_bfloat16& h, __nv_bfloat16& l) {
    h = __float2bfloat16(x);
    l = __float2bfloat16(x - __bfloat162float(h));
}
__device__ __forceinline__ void mma16816(float* c, const uint32_t* a, const uint32_t* b) {
    asm volatile(
        "mma.sync.aligned.m16n8k16.row.col.f32.bf16.bf16.f32 "
        "{%0,%1,%2,%3}, {%4,%5,%6,%7}, {%8,%9}, {%0,%1,%2,%3};"
        : "+f"(c[0]), "+f"(c[1]), "+f"(c[2]), "+f"(c[3])
        : "r"(a[0]), "r"(a[1]), "r"(a[2]), "r"(a[3]), "r"(b[0]), "r"(b[1]));
}

// ---------------------------------------------------------------------------
// GEMM: C = A(M x 512) @ W^T, W is (N,512) row-major.
// Block 128x128, 8 warps (2m x 4n), warp tile 64x32, k-chunk 32.
// MODE 0: A = x (arg), scatter epilogue to q/k/v.
// MODE 1: A = g_att (device symbol!), bias epilogue to out.
// ---------------------------------------------------------------------------
constexpr int GSTR = 40;  // bf16 stride for 32-k tiles (conflict-free frag loads)

template <int MODE>
__global__ __launch_bounds__(256, 2)
void mma_gemm(const float* __restrict__ Ain, const float* __restrict__ W,
              const float* __restrict__ bias, float* __restrict__ out) {
    __shared__ __nv_bfloat16 Ahi[128 * GSTR], Alo[128 * GSTR];
    __shared__ __nv_bfloat16 Bhi[128 * GSTR], Blo[128 * GSTR];

    // CRITICAL: device-symbol A source must be resolved in DEVICE code.
    const float* A = (MODE == 0) ? Ain : (const float*)g_att;

    const int tid = threadIdx.x;
    const int lane = tid & 31, warp = tid >> 5;
    const int wm = warp >> 2, wn = warp & 3;
    const int bm = blockIdx.x * 128, bn = blockIdx.y * 128;
    const int lrow = tid >> 1, lcb = (tid & 1) * 16;

    const float* Ap = A + (size_t)(bm + lrow) * CC + lcb;
    const float* Wp = W + (size_t)(bn + lrow) * CC + lcb;

    float acc[4][4][4];
#pragma unroll
    for (int i = 0; i < 4; i++)
#pragma unroll
        for (int j = 0; j < 4; j++)
#pragma unroll
            for (int r = 0; r < 4; r++) acc[i][j][r] = 0.0f;

    for (int k0 = 0; k0 < CC; k0 += 32) {
        float4 av[4], wv[4];
#pragma unroll
        for (int u = 0; u < 4; u++) {
            av[u] = *(const float4*)(Ap + k0 + 4 * u);
            wv[u] = *(const float4*)(Wp + k0 + 4 * u);
        }
        __syncthreads();
#pragma unroll
        for (int u = 0; u < 4; u++) {
            const int c = lcb + 4 * u;
            __nv_bfloat16 h0, l0, h1, l1, h2, l2, h3, l3;
            split2(av[u].x, h0, l0); split2(av[u].y, h1, l1);
            split2(av[u].z, h2, l2); split2(av[u].w, h3, l3);
            *(uint32_t*)&Ahi[lrow * GSTR + c]     = pack2(h0, h1);
            *(uint32_t*)&Ahi[lrow * GSTR + c + 2] = pack2(h2, h3);
            *(uint32_t*)&Alo[lrow * GSTR + c]     = pack2(l0, l1);
            *(uint32_t*)&Alo[lrow * GSTR + c + 2] = pack2(l2, l3);
            split2(wv[u].x, h0, l0); split2(wv[u].y, h1, l1);
            split2(wv[u].z, h2, l2); split2(wv[u].w, h3, l3);
            *(uint32_t*)&Bhi[lrow * GSTR + c]     = pack2(h0, h1);
            *(uint32_t*)&Bhi[lrow * GSTR + c + 2] = pack2(h2, h3);
            *(uint32_t*)&Blo[lrow * GSTR + c]     = pack2(l0, l1);
            *(uint32_t*)&Blo[lrow * GSTR + c + 2] = pack2(l2, l3);
        }
        __syncthreads();

#pragma unroll
        for (int s = 0; s < 2; s++) {
            uint32_t bh[4][2], bl[4][2];
#pragma unroll
            for (int nt = 0; nt < 4; nt++) {
                const int off = (wn * 32 + nt * 8 + (lane >> 2)) * GSTR + s * 16 + 2 * (lane & 3);
                bh[nt][0] = *(const uint32_t*)&Bhi[off];
                bh[nt][1] = *(const uint32_t*)&Bhi[off + 8];
                bl[nt][0] = *(const uint32_t*)&Blo[off];
                bl[nt][1] = *(const uint32_t*)&Blo[off + 8];
            }
#pragma unroll
            for (int mt = 0; mt < 4; mt++) {
                const int off = (wm * 64 + mt * 16 + (lane >> 2)) * GSTR + s * 16 + 2 * (lane & 3);
                uint32_t ah[4] = {
                    *(const uint32_t*)&Ahi[off],
                    *(const uint32_t*)&Ahi[off + 8 * GSTR],
                    *(const uint32_t*)&Ahi[off + 8],
                    *(const uint32_t*)&Ahi[off + 8 * GSTR + 8]
                };
                uint32_t al[4] = {
                    *(const uint32_t*)&Alo[off],
                    *(const uint32_t*)&Alo[off + 8 * GSTR],
                    *(const uint32_t*)&Alo[off + 8],
                    *(const uint32_t*)&Alo[off + 8 * GSTR + 8]
                };
#pragma unroll
                for (int nt = 0; nt < 4; nt++) {
                    mma16816(acc[mt][nt], ah, bh[nt]);
                    mma16816(acc[mt][nt], ah, bl[nt]);
                    mma16816(acc[mt][nt], al, bh[nt]);
                }
            }
        }
    }

    // Epilogue
#pragma unroll
    for (int mt = 0; mt < 4; mt++) {
#pragma unroll
        for (int nt = 0; nt < 4; nt++) {
            const int rA = bm + wm * 64 + mt * 16 + (lane >> 2);
            const int rB = rA + 8;
            const int o = bn + wn * 32 + nt * 8 + 2 * (lane & 3);
            if (MODE == 0) {
                const int part = o >> 9, h = (o >> 6) & 7, d = o & 63;
                float* dst = (part == 0) ? g_q : ((part == 1) ? g_k : g_v);
                {
                    const int b = rA / NN, n = rA - b * NN;
                    *(float2*)&dst[(((size_t)b * HH + h) * NN + n) * DD + d] =
                        make_float2(acc[mt][nt][0], acc[mt][nt][1]);
                }
                {
                    const int b = rB / NN, n = rB - b * NN;
                    *(float2*)&dst[(((size_t)b * HH + h) * NN + n) * DD + d] =
                        make_float2(acc[mt][nt][2], acc[mt][nt][3]);
                }
            } else {
                const float b0 = bias[o], b1 = bias[o + 1];
                *(float2*)&out[(size_t)rA * CC + o] =
                    make_float2(acc[mt][nt][0] + b0, acc[mt][nt][1] + b1);
                *(float2*)&out[(size_t)rB * CC + o] =
                    make_float2(acc[mt][nt][2] + b0, acc[mt][nt][3] + b1);
            }
        }
    }
}

// ---------------------------------------------------------------------------
// Flash attention w/ locality bias, bf16x3 MMA.
// Block = 128 queries x one (b,h). 8 warps, each warp 16 q rows.
// ---------------------------------------------------------------------------
constexpr int KSTR = 72;  // bf16 stride for 64-wide tiles
constexpr int FL_SMEM = (4 * 64 * KSTR + 8 * 2 * 16 * KSTR) * 2;  // 73728 B

__global__ __launch_bounds__(256, 1)
void flash_mma(const float* __restrict__ temp, const float* __restrict__ lw) {
    extern __shared__ __nv_bfloat16 sb[];
    __nv_bfloat16* Khi  = sb;
    __nv_bfloat16* Klo  = sb + 64 * KSTR;
    __nv_bfloat16* Vthi = sb + 2 * 64 * KSTR;
    __nv_bfloat16* Vtlo = sb + 3 * 64 * KSTR;

    const int tid = threadIdx.x;
    const int lane = tid & 31, warp = tid >> 5;
    __nv_bfloat16* Phi = sb + 4 * 64 * KSTR + warp * (2 * 16 * KSTR);
    __nv_bfloat16* Plo = Phi + 16 * KSTR;
    float* Qst = (float*)sb;  // staging, stride 68, reused region

    const int qbase = blockIdx.x * 128;
    const int bh = blockIdx.y;
    const int h = bh & 7, b = bh >> 3;
    const float* Qg = g_q + (size_t)bh * NN * DD;
    const float* Kg = g_k + (size_t)bh * NN * DD;
    const float* Vg = g_v + (size_t)bh * NN * DD;

    const float scale = __expf(temp[h]);
    const float wb = lw[h] * (1.0f / 4418.0f);  // / (2*47^2)

    // Stage Q (128x64) into smem
#pragma unroll
    for (int u = 0; u < 8; u++) {
        const int f4i = tid + 256 * u;
        const int row = f4i >> 4, c4 = (f4i & 15) * 4;
        *(float4*)&Qst[row * 68 + c4] =
            *(const float4*)(Qg + (size_t)(qbase + row) * DD + c4);
    }
    __syncthreads();

    // Q fragments (hi/lo split), kept in registers
    uint32_t qh[4][4], ql[4][4];
    const int qr = warp * 16 + (lane >> 2);
#pragma unroll
    for (int s = 0; s < 4; s++) {
        const int d0 = s * 16 + 2 * (lane & 3);
        const int rows[4] = {qr, qr + 8, qr, qr + 8};
        const int cols[4] = {d0, d0, d0 + 8, d0 + 8};
#pragma unroll
        for (int j = 0; j < 4; j++) {
            const float f0 = Qst[rows[j] * 68 + cols[j]];
            const float f1 = Qst[rows[j] * 68 + cols[j] + 1];
            __nv_bfloat16 h0, l0, h1, l1;
            split2(f0, h0, l0); split2(f1, h1, l1);
            qh[s][j] = pack2(h0, h1);
            ql[s][j] = pack2(l0, l1);
        }
    }
    __syncthreads();

    float oacc[8][4];
#pragma unroll
    for (int u = 0; u < 8; u++)
#pragma unroll
        for (int r = 0; r < 4; r++) oacc[u][r] = 0.0f;
    float mA = -1e30f, mB = -1e30f, lA = 0.0f, lB = 0.0f;

    const int qA = qbase + qr, qB = qA + 8;
    const int qyA = qA / GG, qxA = qA - qyA * GG;
    const int qyB = qB / GG, qxB = qB - qyB * GG;
    const float fqyA = (float)qyA, fqxA = (float)qxA;
    const float fqyB = (float)qyB, fqxB = (float)qxB;

    const int lr = tid >> 2;        // 0..63 (key row on loads)
    const int lc = (tid & 3) * 16;  // d base

    for (int kt = 0; kt < NN / 64; kt++) {
        const int k0 = kt * 64;
        __syncthreads();
        // Load K (row-major) and V (transposed, d-major), split hi/lo
#pragma unroll
        for (int u = 0; u < 4; u++) {
            const int c = lc + 4 * u;
            float4 kv = *(const float4*)(Kg + (size_t)(k0 + lr) * DD + c);
            __nv_bfloat16 h0, l0, h1, l1, h2, l2, h3, l3;
            split2(kv.x, h0, l0); split2(kv.y, h1, l1);
            split2(kv.z, h2, l2); split2(kv.w, h3, l3);
            *(uint32_t*)&Khi[lr * KSTR + c]     = pack2(h0, h1);
            *(uint32_t*)&Khi[lr * KSTR + c + 2] = pack2(h2, h3);
            *(uint32_t*)&Klo[lr * KSTR + c]     = pack2(l0, l1);
            *(uint32_t*)&Klo[lr * KSTR + c + 2] = pack2(l2, l3);
            float4 vv = *(const float4*)(Vg + (size_t)(k0 + lr) * DD + c);
            split2(vv.x, h0, l0); split2(vv.y, h1, l1);
            split2(vv.z, h2, l2); split2(vv.w, h3, l3);
            Vthi[(c + 0) * KSTR + lr] = h0; Vtlo[(c + 0) * KSTR + lr] = l0;
            Vthi[(c + 1) * KSTR + lr] = h1; Vtlo[(c + 1) * KSTR + lr] = l1;
            Vthi[(c + 2) * KSTR + lr] = h2; Vtlo[(c + 2) * KSTR + lr] = l2;
            Vthi[(c + 3) * KSTR + lr] = h3; Vtlo[(c + 3) * KSTR + lr] = l3;
        }
        __syncthreads();

        // S = Q @ K^T  (16 x 64 per warp)
        float sfr[8][4];
#pragma unroll
        for (int t = 0; t < 8; t++)
#pragma unroll
            for (int r = 0; r < 4; r++) sfr[t][r] = 0.0f;
#pragma unroll
        for (int t = 0; t < 8; t++) {
            const int off = (8 * t + (lane >> 2)) * KSTR + 2 * (lane & 3);
#pragma unroll
            for (int s = 0; s < 4; s++) {
                uint32_t bhh[2] = { *(const uint32_t*)&Khi[off + 16 * s],
                                    *(const uint32_t*)&Khi[off + 16 * s + 8] };
                uint32_t bll[2] = { *(const uint32_t*)&Klo[off + 16 * s],
                                    *(const uint32_t*)&Klo[off + 16 * s + 8] };
                mma16816(sfr[t], qh[s], bhh);
                mma16816(sfr[t], qh[s], bll);
                mma16816(sfr[t], ql[s], bhh);
            }
        }

        // scale + locality bias + row max
        float tmA = -1e30f, tmB = -1e30f;
#pragma unroll
        for (int t = 0; t < 8; t++) {
#pragma unroll
            for (int j = 0; j < 2; j++) {
                const int k = k0 + 8 * t + 2 * (lane & 3) + j;
                const int ky = k / GG;
                const float fky = (float)ky, fkx = (float)(k - ky * GG);
                float dy = fqyA - fky, dx = fqxA - fkx;
                sfr[t][j] = sfr[t][j] * scale - wb * (dy * dy + dx * dx);
                dy = fqyB - fky; dx = fqxB - fkx;
                sfr[t][2 + j] = sfr[t][2 + j] * scale - wb * (dy * dy + dx * dx);
                tmA = fmaxf(tmA, sfr[t][j]);
                tmB = fmaxf(tmB, sfr[t][2 + j]);
            }
        }
        tmA = fmaxf(tmA, __shfl_xor_sync(0xffffffffu, tmA, 1));
        tmA = fmaxf(tmA, __shfl_xor_sync(0xffffffffu, tmA, 2));
        tmB = fmaxf(tmB, __shfl_xor_sync(0xffffffffu, tmB, 1));
        tmB = fmaxf(tmB, __shfl_xor_sync(0xffffffffu, tmB, 2));
        const float mnA = fmaxf(mA, tmA), mnB = fmaxf(mB, tmB);
        const float facA = __expf(mA - mnA), facB = __expf(mB - mnB);
        mA = mnA; mB = mnB;

        float rsA = 0.0f, rsB = 0.0f;
#pragma unroll
        for (int t = 0; t < 8; t++) {
            const float p0 = __expf(sfr[t][0] - mnA);
            const float p1 = __expf(sfr[t][1] - mnA);
            const float p2 = __expf(sfr[t][2] - mnB);
            const float p3 = __expf(sfr[t][3] - mnB);
            rsA += p0 + p1; rsB += p2 + p3;
            const int col = 8 * t + 2 * (lane & 3);
            __nv_bfloat16 h0, l0, h1, l1;
            split2(p0, h0, l0); split2(p1, h1, l1);
            *(uint32_t*)&Phi[(lane >> 2) * KSTR + col] = pack2(h0, h1);
            *(uint32_t*)&Plo[(lane >> 2) * KSTR + col] = pack2(l0, l1);
            split2(p2, h0, l0); split2(p3, h1, l1);
            *(uint32_t*)&Phi[((lane >> 2) + 8) * KSTR + col] = pack2(h0, h1);
            *(uint32_t*)&Plo[((lane >> 2) + 8) * KSTR + col] = pack2(l0, l1);
        }
        rsA += __shfl_xor_sync(0xffffffffu, rsA, 1);
        rsA += __shfl_xor_sync(0xffffffffu, rsA, 2);
        rsB += __shfl_xor_sync(0xffffffffu, rsB, 1);
        rsB += __shfl_xor_sync(0xffffffffu, rsB, 2);
        lA = lA * facA + rsA;
        lB = lB * facB + rsB;
#pragma unroll
        for (int u = 0; u < 8; u++) {
            oacc[u][0] *= facA; oacc[u][1] *= facA;
            oacc[u][2] *= facB; oacc[u][3] *= facB;
        }
        __syncwarp();

        // O += P @ V
#pragma unroll
        for (int s = 0; s < 4; s++) {
            const int poff = (lane >> 2) * KSTR + 16 * s + 2 * (lane & 3);
            uint32_t ah[4] = { *(const uint32_t*)&Phi[poff],
                               *(const uint32_t*)&Phi[poff + 8 * KSTR],
                               *(const uint32_t*)&Phi[poff + 8],
                               *(const uint32_t*)&Phi[poff + 8 * KSTR + 8] };
            uint32_t al[4] = { *(const uint32_t*)&Plo[poff],
                               *(const uint32_t*)&Plo[poff + 8 * KSTR],
                               *(const uint32_t*)&Plo[poff + 8],
                               *(const uint32_t*)&Plo[poff + 8 * KSTR + 8] };
#pragma unroll
            for (int u = 0; u < 8; u++) {
                const int voff = (8 * u + (lane >> 2)) * KSTR + 16 * s + 2 * (lane & 3);
                uint32_t bhh[2] = { *(const uint32_t*)&Vthi[voff],
                                    *(const uint32_t*)&Vthi[voff + 8] };
                uint32_t bll[2] = { *(const uint32_t*)&Vtlo[voff],
                                    *(const uint32_t*)&Vtlo[voff + 8] };
                mma16816(oacc[u], ah, bhh);
                mma16816(oacc[u], ah, bll);
                mma16816(oacc[u], al, bhh);
            }
        }
    }

    // epilogue: normalize & write (B, N, C)
    const float invA = 1.0f / lA, invB = 1.0f / lB;
    float* oA = g_att + ((size_t)(b * NN + qA)) * CC + h * DD;
    float* oB = g_att + ((size_t)(b * NN + qB)) * CC + h * DD;
#pragma unroll
    for (int u = 0; u < 8; u++) {
        const int c = 8 * u + 2 * (lane & 3);
        *(float2*)&oA[c] = make_float2(oacc[u][0] * invA, oacc[u][1] * invA);
        *(float2*)&oB[c] = make_float2(oacc[u][2] * invB, oacc[u][3] * invB);
    }
}

// ---------------------------------------------------------------------------
extern "C" void kernel_launch(void* const* d_in, const int* in_sizes, int n_in,
                              void* d_out, int out_size) {
    const float* x      = (const float*)d_in[0];  // (B, N, C)
    const float* qkv_w  = (const float*)d_in[1];  // (3C, C)
    const float* proj_w = (const float*)d_in[2];  // (C, C)
    const float* proj_b = (const float*)d_in[3];  // (C,)
    const float* temp   = (const float*)d_in[4];  // (H,1,1)
    const float* lw     = (const float*)d_in[5];  // (H,)
    float* out = (float*)d_out;

    mma_gemm<0><<<dim3(M_TOT / 128, (3 * CC) / 128), 256>>>(x, qkv_w, nullptr, nullptr);

    cudaFuncSetAttribute(flash_mma, cudaFuncAttributeMaxDynamicSharedMemorySize,
                         FL_SMEM);
    flash_mma<<<dim3(NN / 128, BB * HH), 256, FL_SMEM>>>(temp, lw);

    mma_gemm<1><<<dim3(M_TOT / 128, CC / 128), 256>>>(nullptr, proj_w, proj_b, out);
}

// round 4
// speedup vs baseline: 3.1030x; 1.4235x over previous
#include <cuda_runtime.h>
#include <cuda_bf16.h>
#include <stdint.h>

// LocalitySelfAttention: B=8, N=2304 (48x48), C=512, H=8, D=64.
// bf16x3 error-split MMA everywhere; all operands pre-split to bf16 hi/lo in
// global, cp.async tile loads, ldmatrix fragment loads, register-resident P.

constexpr int BB = 8;
constexpr int NN = 2304;
constexpr int CC = 512;
constexpr int HH = 8;
constexpr int DD = 64;
constexpr int GG = 48;
constexpr int M_TOT = BB * NN;          // 18432
constexpr size_t SX  = (size_t)M_TOT * CC;   // 9437184 (also = BB*HH*NN*DD)
constexpr size_t SQW = (size_t)1536 * 512;
constexpr size_t SPW = (size_t)512 * 512;

// bf16 hi/lo scratch (device globals; no runtime allocation)
__device__ __nv_bfloat16 g_xh[SX],  g_xl[SX];
__device__ __nv_bfloat16 g_wqh[SQW], g_wql[SQW];
__device__ __nv_bfloat16 g_wph[SPW], g_wpl[SPW];
__device__ __nv_bfloat16 g_qh[SX],  g_ql[SX];   // [bh][n][d]
__device__ __nv_bfloat16 g_kh[SX],  g_kl[SX];   // [bh][n][d]
__device__ __nv_bfloat16 g_vth[SX], g_vtl[SX];  // [bh][d][n]  (pre-transposed)
__device__ __nv_bfloat16 g_ath[SX], g_atl[SX];  // [b][n][C]

__device__ __forceinline__ uint32_t pack2(__nv_bfloat16 a, __nv_bfloat16 b) {
    __nv_bfloat162 t; t.x = a; t.y = b;
    return *reinterpret_cast<uint32_t*>(&t);
}
__device__ __forceinline__ void split2(float x, __nv_bfloat16& h, __nv_bfloat16& l) {
    h = __float2bfloat16(x);
    l = __float2bfloat16(x - __bfloat162float(h));
}
__device__ __forceinline__ void mma16816(float* c, const uint32_t* a, const uint32_t* b) {
    asm volatile(
        "mma.sync.aligned.m16n8k16.row.col.f32.bf16.bf16.f32 "
        "{%0,%1,%2,%3}, {%4,%5,%6,%7}, {%8,%9}, {%0,%1,%2,%3};"
        : "+f"(c[0]), "+f"(c[1]), "+f"(c[2]), "+f"(c[3])
        : "r"(a[0]), "r"(a[1]), "r"(a[2]), "r"(a[3]), "r"(b[0]), "r"(b[1]));
}
__device__ __forceinline__ void ldsm_x4(uint32_t* r, uint32_t addr) {
    asm volatile("ldmatrix.sync.aligned.m8n8.x4.shared.b16 {%0,%1,%2,%3}, [%4];"
        : "=r"(r[0]), "=r"(r[1]), "=r"(r[2]), "=r"(r[3]) : "r"(addr));
}
__device__ __forceinline__ uint32_t s2u(const void* p) {
    return (uint32_t)__cvta_generic_to_shared(p);
}
__device__ __forceinline__ void cpa16(uint32_t s, const void* g) {
    asm volatile("cp.async.ca.shared.global [%0], [%1], 16;" :: "r"(s), "l"(g));
}
#define CP_COMMIT() asm volatile("cp.async.commit_group;")
#define CP_WAIT0()  asm volatile("cp.async.wait_group 0;")

// ---------------------------------------------------------------------------
// Prep: split fp32 inputs into bf16 hi/lo global arrays (one pass, mem-bound).
// ---------------------------------------------------------------------------
__global__ __launch_bounds__(256)
void prep_split(const float* __restrict__ x, const float* __restrict__ wq,
                const float* __restrict__ wp) {
    const size_t i4 = ((size_t)blockIdx.x * 256 + threadIdx.x) * 4;
    const float* src; __nv_bfloat16 *dh, *dl; size_t off;
    if (i4 < SX)                  { src = x;  dh = g_xh;  dl = g_xl;  off = i4; }
    else if (i4 < SX + SQW)       { src = wq; dh = g_wqh; dl = g_wql; off = i4 - SX; }
    else if (i4 < SX + SQW + SPW) { src = wp; dh = g_wph; dl = g_wpl; off = i4 - SX - SQW; }
    else return;
    const float4 v = *(const float4*)(src + off);
    __nv_bfloat16 h0, l0, h1, l1, h2, l2, h3, l3;
    split2(v.x, h0, l0); split2(v.y, h1, l1);
    split2(v.z, h2, l2); split2(v.w, h3, l3);
    *(uint32_t*)&dh[off]     = pack2(h0, h1);
    *(uint32_t*)&dh[off + 2] = pack2(h2, h3);
    *(uint32_t*)&dl[off]     = pack2(l0, l1);
    *(uint32_t*)&dl[off + 2] = pack2(l2, l3);
}

// ---------------------------------------------------------------------------
// GEMM: block 128x128, k-chunk 32, 8 warps (2m x 4n), warp tile 64x32.
// MODE 0: A=g_xh/l, B=g_wqh/l, epilogue scatter to q/k (bf16 hi/lo) + vt.
// MODE 1: A=g_ath/l, B=g_wph/l, epilogue fp32 out + bias.
// ---------------------------------------------------------------------------
constexpr int GSTR = 40;  // bf16 row stride (80B: 16B-aligned, LDSM conflict-free)

template <int MODE>
__global__ __launch_bounds__(256, 2)
void mma_gemm(const float* __restrict__ bias, float* __restrict__ out) {
    __shared__ __nv_bfloat16 sAh[128 * GSTR], sAl[128 * GSTR];
    __shared__ __nv_bfloat16 sBh[128 * GSTR], sBl[128 * GSTR];

    const __nv_bfloat16* Ah = (MODE == 0) ? g_xh : g_ath;
    const __nv_bfloat16* Al = (MODE == 0) ? g_xl : g_atl;
    const __nv_bfloat16* Bh = (MODE == 0) ? g_wqh : g_wph;
    const __nv_bfloat16* Bl = (MODE == 0) ? g_wql : g_wpl;

    const int tid = threadIdx.x;
    const int lane = tid & 31, warp = tid >> 5;
    const int wm = warp >> 2, wn = warp & 3;
    const int bm = blockIdx.x * 128, bn = blockIdx.y * 128;

    float acc[4][4][4];
#pragma unroll
    for (int i = 0; i < 4; i++)
#pragma unroll
        for (int j = 0; j < 4; j++)
#pragma unroll
            for (int r = 0; r < 4; r++) acc[i][j][r] = 0.0f;

    for (int k0 = 0; k0 < CC; k0 += 32) {
        // cp.async: 4 arrays x 512 16B-chunks; 2 chunks/thread/array
#pragma unroll
        for (int it = 0; it < 2; it++) {
            const int c = tid + 256 * it;
            const int row = c >> 2, col = c & 3;  // col in 16B units (8 elems)
            const size_t ga = (size_t)(bm + row) * CC + k0 + col * 8;
            const size_t gb = (size_t)(bn + row) * CC + k0 + col * 8;
            const int so = row * GSTR + col * 8;
            cpa16(s2u(&sAh[so]), &Ah[ga]);
            cpa16(s2u(&sAl[so]), &Al[ga]);
            cpa16(s2u(&sBh[so]), &Bh[gb]);
            cpa16(s2u(&sBl[so]), &Bl[gb]);
        }
        CP_COMMIT();
        CP_WAIT0();
        __syncthreads();

        // B fragments: per nt one ldsm.x4 covers s0+s1 (k 0..31)
        uint32_t bh_[4][4], bl_[4][4];
#pragma unroll
        for (int nt = 0; nt < 4; nt++) {
            const int boff = (wn * 32 + nt * 8 + (lane & 7)) * GSTR + (lane >> 3) * 8;
            ldsm_x4(bh_[nt], s2u(&sBh[boff]));
            ldsm_x4(bl_[nt], s2u(&sBl[boff]));
        }
#pragma unroll
        for (int mt = 0; mt < 4; mt++) {
            uint32_t ah[2][4], al[2][4];
#pragma unroll
            for (int s = 0; s < 2; s++) {
                const int aoff = (wm * 64 + mt * 16 + (lane & 15)) * GSTR + s * 16 + (lane >> 4) * 8;
                ldsm_x4(ah[s], s2u(&sAh[aoff]));
                ldsm_x4(al[s], s2u(&sAl[aoff]));
            }
#pragma unroll
            for (int s = 0; s < 2; s++)
#pragma unroll
                for (int nt = 0; nt < 4; nt++) {
                    mma16816(acc[mt][nt], ah[s], &bh_[nt][2 * s]);
                    mma16816(acc[mt][nt], ah[s], &bl_[nt][2 * s]);
                    mma16816(acc[mt][nt], al[s], &bh_[nt][2 * s]);
                }
        }
        __syncthreads();
    }

    // Epilogue
#pragma unroll
    for (int mt = 0; mt < 4; mt++) {
#pragma unroll
        for (int nt = 0; nt < 4; nt++) {
            const int rA = bm + wm * 64 + mt * 16 + (lane >> 2);
            const int rB = rA + 8;
            const int o = bn + wn * 32 + nt * 8 + 2 * (lane & 3);
            if (MODE == 0) {
                const int part = o >> 9, h = (o >> 6) & 7, d = o & 63;
                const int bA = rA / NN, nA = rA - bA * NN;
                const int bB = rB / NN, nB = rB - bB * NN;
                const int bhA = bA * HH + h, bhB = bB * HH + h;
                __nv_bfloat16 h0, l0, h1, l1, h2, l2, h3, l3;
                split2(acc[mt][nt][0], h0, l0); split2(acc[mt][nt][1], h1, l1);
                split2(acc[mt][nt][2], h2, l2); split2(acc[mt][nt][3], h3, l3);
                if (part == 2) {
                    // V transposed: [bh][d][n]
                    const size_t iA = ((size_t)bhA * DD + d) * NN + nA;
                    const size_t iB = ((size_t)bhB * DD + d) * NN + nB;
                    g_vth[iA] = h0; g_vtl[iA] = l0;
                    g_vth[iA + NN] = h1; g_vtl[iA + NN] = l1;
                    g_vth[iB] = h2; g_vtl[iB] = l2;
                    g_vth[iB + NN] = h3; g_vtl[iB + NN] = l3;
                } else {
                    __nv_bfloat16* dh = (part == 0) ? g_qh : g_kh;
                    __nv_bfloat16* dl = (part == 0) ? g_ql : g_kl;
                    const size_t iA = ((size_t)bhA * NN + nA) * DD + d;
                    const size_t iB = ((size_t)bhB * NN + nB) * DD + d;
                    *(uint32_t*)&dh[iA] = pack2(h0, h1);
                    *(uint32_t*)&dl[iA] = pack2(l0, l1);
                    *(uint32_t*)&dh[iB] = pack2(h2, h3);
                    *(uint32_t*)&dl[iB] = pack2(l2, l3);
                }
            } else {
                const float b0 = bias[o], b1 = bias[o + 1];
                *(float2*)&out[(size_t)rA * CC + o] =
                    make_float2(acc[mt][nt][0] + b0, acc[mt][nt][1] + b1);
                *(float2*)&out[(size_t)rB * CC + o] =
                    make_float2(acc[mt][nt][2] + b0, acc[mt][nt][3] + b1);
            }
        }
    }
}

// ---------------------------------------------------------------------------
// Flash attention w/ locality bias. CTA = 64 queries x one (b,h), 4 warps.
// K tiles [n][d], V tiles pre-transposed [d][n]; all bf16 hi/lo via cp.async.
// P kept in registers (C-frag layout == A-frag layout).
// ---------------------------------------------------------------------------
constexpr int FSTR = 72;  // 144B rows: 16B-aligned, LDSM conflict-free

__global__ __launch_bounds__(128, 2)
void flash_mma(const float* __restrict__ temp, const float* __restrict__ lw) {
    __shared__ __nv_bfloat16 sKh[64 * FSTR], sKl[64 * FSTR];
    __shared__ __nv_bfloat16 sVh[64 * FSTR], sVl[64 * FSTR];

    const int tid = threadIdx.x;
    const int lane = tid & 31, warp = tid >> 5;
    const int q0 = blockIdx.x * 64;
    const int bh = blockIdx.y;
    const int h = bh & 7, b = bh >> 3;

    const __nv_bfloat16* Qh = g_qh + (size_t)bh * NN * DD;
    const __nv_bfloat16* Ql = g_ql + (size_t)bh * NN * DD;
    const __nv_bfloat16* Kh = g_kh + (size_t)bh * NN * DD;
    const __nv_bfloat16* Kl = g_kl + (size_t)bh * NN * DD;
    const __nv_bfloat16* Vh = g_vth + (size_t)bh * NN * DD;  // [d][n]
    const __nv_bfloat16* Vl = g_vtl + (size_t)bh * NN * DD;

    const float scale = __expf(temp[h]);
    const float wb = lw[h] * (1.0f / 4418.0f);  // / (2*47^2)

    // Stage Q (64x64) through sKh/sKl, extract fragments
#pragma unroll
    for (int it = 0; it < 4; it++) {
        const int c = tid + 128 * it;          // 512 chunks per array
        const int row = c >> 3, col = c & 7;
        const size_t g = (size_t)(q0 + row) * DD + col * 8;
        const int so = row * FSTR + col * 8;
        cpa16(s2u(&sKh[so]), &Qh[g]);
        cpa16(s2u(&sKl[so]), &Ql[g]);
    }
    CP_COMMIT();
    CP_WAIT0();
    __syncthreads();

    uint32_t qh[4][4], ql[4][4];
#pragma unroll
    for (int s = 0; s < 4; s++) {
        const int off = (warp * 16 + (lane & 15)) * FSTR + s * 16 + (lane >> 4) * 8;
        ldsm_x4(qh[s], s2u(&sKh[off]));
        ldsm_x4(ql[s], s2u(&sKl[off]));
    }
    __syncthreads();

    float oacc[8][4];
#pragma unroll
    for (int u = 0; u < 8; u++)
#pragma unroll
        for (int r = 0; r < 4; r++) oacc[u][r] = 0.0f;
    float mA = -1e30f, mB = -1e30f, lA = 0.0f, lB = 0.0f;

    const int qA = q0 + warp * 16 + (lane >> 2), qB = qA + 8;
    const int qyA = qA / GG, qyB = qB / GG;
    const float fqyA = (float)qyA, fqxA = (float)(qA - qyA * GG);
    const float fqyB = (float)qyB, fqxB = (float)(qB - qyB * GG);

    for (int kt = 0; kt < NN / 64; kt++) {
        const int k0 = kt * 64;
        // Load K tile [n][d] and V^T tile [d][n0..n0+63]
#pragma unroll
        for (int it = 0; it < 4; it++) {
            const int c = tid + 128 * it;
            const int row = c >> 3, col = c & 7;
            const size_t gk = (size_t)(k0 + row) * DD + col * 8;
            const size_t gv = (size_t)row * NN + k0 + col * 8;
            const int so = row * FSTR + col * 8;
            cpa16(s2u(&sKh[so]), &Kh[gk]);
            cpa16(s2u(&sKl[so]), &Kl[gk]);
            cpa16(s2u(&sVh[so]), &Vh[gv]);
            cpa16(s2u(&sVl[so]), &Vl[gv]);
        }
        CP_COMMIT();
        CP_WAIT0();
        __syncthreads();

        // S = Q @ K^T  (16 x 64 per warp)
        float sfr[8][4];
#pragma unroll
        for (int t = 0; t < 8; t++)
#pragma unroll
            for (int r = 0; r < 4; r++) sfr[t][r] = 0.0f;
#pragma unroll
        for (int t = 0; t < 8; t++) {
            const int base = (8 * t + (lane & 7)) * FSTR + (lane >> 3) * 8;
            uint32_t k0h[4], k1h[4], k0l[4], k1l[4];
            ldsm_x4(k0h, s2u(&sKh[base]));
            ldsm_x4(k1h, s2u(&sKh[base + 32]));
            ldsm_x4(k0l, s2u(&sKl[base]));
            ldsm_x4(k1l, s2u(&sKl[base + 32]));
            mma16816(sfr[t], qh[0], &k0h[0]); mma16816(sfr[t], qh[0], &k0l[0]); mma16816(sfr[t], ql[0], &k0h[0]);
            mma16816(sfr[t], qh[1], &k0h[2]); mma16816(sfr[t], qh[1], &k0l[2]); mma16816(sfr[t], ql[1], &k0h[2]);
            mma16816(sfr[t], qh[2], &k1h[0]); mma16816(sfr[t], qh[2], &k1l[0]); mma16816(sfr[t], ql[2], &k1h[0]);
            mma16816(sfr[t], qh[3], &k1h[2]); mma16816(sfr[t], qh[3], &k1l[2]); mma16816(sfr[t], ql[3], &k1h[2]);
        }

        // scale + locality bias + row max
        float tmA = -1e30f, tmB = -1e30f;
#pragma unroll
        for (int t = 0; t < 8; t++) {
#pragma unroll
            for (int j = 0; j < 2; j++) {
                const int k = k0 + 8 * t + 2 * (lane & 3) + j;
                const int ky = k / GG;
                const float fky = (float)ky, fkx = (float)(k - ky * GG);
                float dy = fqyA - fky, dx = fqxA - fkx;
                sfr[t][j] = sfr[t][j] * scale - wb * (dy * dy + dx * dx);
                dy = fqyB - fky; dx = fqxB - fkx;
                sfr[t][2 + j] = sfr[t][2 + j] * scale - wb * (dy * dy + dx * dx);
                tmA = fmaxf(tmA, sfr[t][j]);
                tmB = fmaxf(tmB, sfr[t][2 + j]);
            }
        }
        tmA = fmaxf(tmA, __shfl_xor_sync(0xffffffffu, tmA, 1));
        tmA = fmaxf(tmA, __shfl_xor_sync(0xffffffffu, tmA, 2));
        tmB = fmaxf(tmB, __shfl_xor_sync(0xffffffffu, tmB, 1));
        tmB = fmaxf(tmB, __shfl_xor_sync(0xffffffffu, tmB, 2));
        const float mnA = fmaxf(mA, tmA), mnB = fmaxf(mB, tmB);
        const float facA = __expf(mA - mnA), facB = __expf(mB - mnB);
        mA = mnA; mB = mnB;

        // exp + pack P fragments in registers (A-frag layout)
        uint32_t ah[4][4], al[4][4];
        float rsA = 0.0f, rsB = 0.0f;
#pragma unroll
        for (int s = 0; s < 4; s++) {
            const float p0 = __expf(sfr[2 * s][0] - mnA);
            const float p1 = __expf(sfr[2 * s][1] - mnA);
            const float p2 = __expf(sfr[2 * s][2] - mnB);
            const float p3 = __expf(sfr[2 * s][3] - mnB);
            const float r0 = __expf(sfr[2 * s + 1][0] - mnA);
            const float r1 = __expf(sfr[2 * s + 1][1] - mnA);
            const float r2 = __expf(sfr[2 * s + 1][2] - mnB);
            const float r3 = __expf(sfr[2 * s + 1][3] - mnB);
            rsA += p0 + p1 + r0 + r1;
            rsB += p2 + p3 + r2 + r3;
            __nv_bfloat16 h0, l0, h1, l1;
            split2(p0, h0, l0); split2(p1, h1, l1);
            ah[s][0] = pack2(h0, h1); al[s][0] = pack2(l0, l1);
            split2(p2, h0, l0); split2(p3, h1, l1);
            ah[s][1] = pack2(h0, h1); al[s][1] = pack2(l0, l1);
            split2(r0, h0, l0); split2(r1, h1, l1);
            ah[s][2] = pack2(h0, h1); al[s][2] = pack2(l0, l1);
            split2(r2, h0, l0); split2(r3, h1, l1);
            ah[s][3] = pack2(h0, h1); al[s][3] = pack2(l0, l1);
        }
        rsA += __shfl_xor_sync(0xffffffffu, rsA, 1);
        rsA += __shfl_xor_sync(0xffffffffu, rsA, 2);
        rsB += __shfl_xor_sync(0xffffffffu, rsB, 1);
        rsB += __shfl_xor_sync(0xffffffffu, rsB, 2);
        lA = lA * facA + rsA;
        lB = lB * facB + rsB;
#pragma unroll
        for (int u = 0; u < 8; u++) {
            oacc[u][0] *= facA; oacc[u][1] *= facA;
            oacc[u][2] *= facB; oacc[u][3] *= facB;
        }

        // O += P @ V   (B-frags from pre-transposed V^T rows = d)
#pragma unroll
        for (int u = 0; u < 8; u++) {
            const int base = (8 * u + (lane & 7)) * FSTR + (lane >> 3) * 8;
            uint32_t v0h[4], v1h[4], v0l[4], v1l[4];
            ldsm_x4(v0h, s2u(&sVh[base]));
            ldsm_x4(v1h, s2u(&sVh[base + 32]));
            ldsm_x4(v0l, s2u(&sVl[base]));
            ldsm_x4(v1l, s2u(&sVl[base + 32]));
            mma16816(oacc[u], ah[0], &v0h[0]); mma16816(oacc[u], ah[0], &v0l[0]); mma16816(oacc[u], al[0], &v0h[0]);
            mma16816(oacc[u], ah[1], &v0h[2]); mma16816(oacc[u], ah[1], &v0l[2]); mma16816(oacc[u], al[1], &v0h[2]);
            mma16816(oacc[u], ah[2], &v1h[0]); mma16816(oacc[u], ah[2], &v1l[0]); mma16816(oacc[u], al[2], &v1h[0]);
            mma16816(oacc[u], ah[3], &v1h[2]); mma16816(oacc[u], ah[3], &v1l[2]); mma16816(oacc[u], al[3], &v1h[2]);
        }
        __syncthreads();
    }

    // epilogue: normalize, split, write att bf16 hi/lo [b][n][C]
    const float invA = 1.0f / lA, invB = 1.0f / lB;
    const size_t baseA = ((size_t)(b * NN + qA)) * CC + h * DD;
    const size_t baseB = ((size_t)(b * NN + qB)) * CC + h * DD;
#pragma unroll
    for (int u = 0; u < 8; u++) {
        const int c = 8 * u + 2 * (lane & 3);
        __nv_bfloat16 h0, l0, h1, l1;
        split2(oacc[u][0] * invA, h0, l0); split2(oacc[u][1] * invA, h1, l1);
        *(uint32_t*)&g_ath[baseA + c] = pack2(h0, h1);
        *(uint32_t*)&g_atl[baseA + c] = pack2(l0, l1);
        split2(oacc[u][2] * invB, h0, l0); split2(oacc[u][3] * invB, h1, l1);
        *(uint32_t*)&g_ath[baseB + c] = pack2(h0, h1);
        *(uint32_t*)&g_atl[baseB + c] = pack2(l0, l1);
    }
}

// ---------------------------------------------------------------------------
extern "C" void kernel_launch(void* const* d_in, const int* in_sizes, int n_in,
                              void* d_out, int out_size) {
    const float* x      = (const float*)d_in[0];  // (B, N, C)
    const float* qkv_w  = (const float*)d_in[1];  // (3C, C)
    const float* proj_w = (const float*)d_in[2];  // (C, C)
    const float* proj_b = (const float*)d_in[3];  // (C,)
    const float* temp   = (const float*)d_in[4];  // (H,1,1)
    const float* lw     = (const float*)d_in[5];  // (H,)
    float* out = (float*)d_out;

    const int prep_blocks = (int)((SX + SQW + SPW) / 4 / 256);  // 10240
    prep_split<<<prep_blocks, 256>>>(x, qkv_w, proj_w);

    mma_gemm<0><<<dim3(M_TOT / 128, 1536 / 128), 256>>>(nullptr, nullptr);

    flash_mma<<<dim3(NN / 64, BB * HH), 128>>>(temp, lw);

    mma_gemm<1><<<dim3(M_TOT / 128, CC / 128), 256>>>(proj_b, out);
}

// round 5
// speedup vs baseline: 3.2384x; 1.0436x over previous
#include <cuda_runtime.h>
#include <cuda_bf16.h>
#include <stdint.h>

// LocalitySelfAttention: B=8, N=2304 (48x48), C=512, H=8, D=64.
// bf16x3 error-split MMA; pre-split bf16 hi/lo operands; 2-stage cp.async
// pipelines; ldmatrix fragments; register-resident P; locality via LUT.

constexpr int BB = 8;
constexpr int NN = 2304;
constexpr int CC = 512;
constexpr int HH = 8;
constexpr int DD = 64;
constexpr int GG = 48;
constexpr int M_TOT = BB * NN;          // 18432
constexpr size_t SX  = (size_t)M_TOT * CC;   // 9437184 (also = BB*HH*NN*DD)
constexpr size_t SQW = (size_t)1536 * 512;
constexpr size_t SPW = (size_t)512 * 512;

__device__ __nv_bfloat16 g_xh[SX],  g_xl[SX];
__device__ __nv_bfloat16 g_wqh[SQW], g_wql[SQW];
__device__ __nv_bfloat16 g_wph[SPW], g_wpl[SPW];
__device__ __nv_bfloat16 g_qh[SX],  g_ql[SX];   // [bh][n][d]
__device__ __nv_bfloat16 g_kh[SX],  g_kl[SX];   // [bh][n][d]
__device__ __nv_bfloat16 g_vth[SX], g_vtl[SX];  // [bh][d][n] (pre-transposed)
__device__ __nv_bfloat16 g_ath[SX], g_atl[SX];  // [b][n][C]
__device__ float4 g_loc[NN];                    // (ky, kx, ky^2+kx^2, 0)

__device__ __forceinline__ uint32_t pack2(__nv_bfloat16 a, __nv_bfloat16 b) {
    __nv_bfloat162 t; t.x = a; t.y = b;
    return *reinterpret_cast<uint32_t*>(&t);
}
__device__ __forceinline__ void split2(float x, __nv_bfloat16& h, __nv_bfloat16& l) {
    h = __float2bfloat16(x);
    l = __float2bfloat16(x - __bfloat162float(h));
}
__device__ __forceinline__ void mma16816(float* c, const uint32_t* a, const uint32_t* b) {
    asm volatile(
        "mma.sync.aligned.m16n8k16.row.col.f32.bf16.bf16.f32 "
        "{%0,%1,%2,%3}, {%4,%5,%6,%7}, {%8,%9}, {%0,%1,%2,%3};"
        : "+f"(c[0]), "+f"(c[1]), "+f"(c[2]), "+f"(c[3])
        : "r"(a[0]), "r"(a[1]), "r"(a[2]), "r"(a[3]), "r"(b[0]), "r"(b[1]));
}
__device__ __forceinline__ void ldsm_x4(uint32_t* r, uint32_t addr) {
    asm volatile("ldmatrix.sync.aligned.m8n8.x4.shared.b16 {%0,%1,%2,%3}, [%4];"
        : "=r"(r[0]), "=r"(r[1]), "=r"(r[2]), "=r"(r[3]) : "r"(addr));
}
__device__ __forceinline__ uint32_t s2u(const void* p) {
    return (uint32_t)__cvta_generic_to_shared(p);
}
__device__ __forceinline__ void cpa16(uint32_t s, const void* g) {
    asm volatile("cp.async.ca.shared.global [%0], [%1], 16;" :: "r"(s), "l"(g));
}
#define CP_COMMIT() asm volatile("cp.async.commit_group;")
#define CP_WAIT0()  asm volatile("cp.async.wait_group 0;")
#define CP_WAIT1()  asm volatile("cp.async.wait_group 1;")

// ---------------------------------------------------------------------------
// Prep: split fp32 inputs into bf16 hi/lo + locality LUT.
// ---------------------------------------------------------------------------
__global__ __launch_bounds__(256)
void prep_split(const float* __restrict__ x, const float* __restrict__ wq,
                const float* __restrict__ wp) {
    const size_t gid = (size_t)blockIdx.x * 256 + threadIdx.x;
    if (gid < NN) {
        const int y = (int)(gid / GG), xx = (int)(gid - (size_t)y * GG);
        const float fy = (float)y, fx = (float)xx;
        g_loc[gid] = make_float4(fy, fx, fy * fy + fx * fx, 0.0f);
    }
    const size_t i4 = gid * 4;
    const float* src; __nv_bfloat16 *dh, *dl; size_t off;
    if (i4 < SX)                  { src = x;  dh = g_xh;  dl = g_xl;  off = i4; }
    else if (i4 < SX + SQW)       { src = wq; dh = g_wqh; dl = g_wql; off = i4 - SX; }
    else if (i4 < SX + SQW + SPW) { src = wp; dh = g_wph; dl = g_wpl; off = i4 - SX - SQW; }
    else return;
    const float4 v = *(const float4*)(src + off);
    __nv_bfloat16 h0, l0, h1, l1, h2, l2, h3, l3;
    split2(v.x, h0, l0); split2(v.y, h1, l1);
    split2(v.z, h2, l2); split2(v.w, h3, l3);
    *(uint32_t*)&dh[off]     = pack2(h0, h1);
    *(uint32_t*)&dh[off + 2] = pack2(h2, h3);
    *(uint32_t*)&dl[off]     = pack2(l0, l1);
    *(uint32_t*)&dl[off + 2] = pack2(l2, l3);
}

// ---------------------------------------------------------------------------
// GEMM: block 128x128, k-chunk 32, 8 warps (2m x 4n), 2-stage cp.async pipe.
// MODE 0: x @ Wqkv^T -> scatter q/k (bf16 hi/lo) + v transposed.
// MODE 1: att @ Wproj^T + bias -> fp32 out.
// ---------------------------------------------------------------------------
constexpr int GSTR = 40;                 // bf16 row stride (80B)
constexpr int G_TILE = 128 * GSTR;       // elems per array
constexpr int G_STAGE = 4 * G_TILE;      // Ah, Al, Bh, Bl
constexpr int G_SMEM = 2 * G_STAGE * 2;  // bytes = 81920

template <int MODE>
__global__ __launch_bounds__(256, 2)
void mma_gemm(const float* __restrict__ bias, float* __restrict__ out) {
    extern __shared__ __nv_bfloat16 smem[];

    const __nv_bfloat16* Ah = (MODE == 0) ? g_xh : g_ath;
    const __nv_bfloat16* Al = (MODE == 0) ? g_xl : g_atl;
    const __nv_bfloat16* Bh = (MODE == 0) ? g_wqh : g_wph;
    const __nv_bfloat16* Bl = (MODE == 0) ? g_wql : g_wpl;

    const int tid = threadIdx.x;
    const int lane = tid & 31, warp = tid >> 5;
    const int wm = warp >> 2, wn = warp & 3;
    const int bm = blockIdx.x * 128, bn = blockIdx.y * 128;

    auto load_stage = [&](int s, int k0) {
        __nv_bfloat16* base = smem + s * G_STAGE;
#pragma unroll
        for (int it = 0; it < 2; it++) {
            const int c = tid + 256 * it;
            const int row = c >> 2, col = c & 3;
            const size_t ga = (size_t)(bm + row) * CC + k0 + col * 8;
            const size_t gb = (size_t)(bn + row) * CC + k0 + col * 8;
            const int so = row * GSTR + col * 8;
            cpa16(s2u(base + so), &Ah[ga]);
            cpa16(s2u(base + G_TILE + so), &Al[ga]);
            cpa16(s2u(base + 2 * G_TILE + so), &Bh[gb]);
            cpa16(s2u(base + 3 * G_TILE + so), &Bl[gb]);
        }
        CP_COMMIT();
    };

    float acc[4][4][4];
#pragma unroll
    for (int i = 0; i < 4; i++)
#pragma unroll
        for (int j = 0; j < 4; j++)
#pragma unroll
            for (int r = 0; r < 4; r++) acc[i][j][r] = 0.0f;

    constexpr int NIT = CC / 32;  // 16
    load_stage(0, 0);
    for (int i = 0; i < NIT; i++) {
        if (i + 1 < NIT) { load_stage((i + 1) & 1, (i + 1) * 32); CP_WAIT1(); }
        else             { CP_WAIT0(); }
        __syncthreads();
        const __nv_bfloat16* sAh = smem + (i & 1) * G_STAGE;
        const __nv_bfloat16* sAl = sAh + G_TILE;
        const __nv_bfloat16* sBh = sAh + 2 * G_TILE;
        const __nv_bfloat16* sBl = sAh + 3 * G_TILE;

        uint32_t bh_[4][4], bl_[4][4];
#pragma unroll
        for (int nt = 0; nt < 4; nt++) {
            const int boff = (wn * 32 + nt * 8 + (lane & 7)) * GSTR + (lane >> 3) * 8;
            ldsm_x4(bh_[nt], s2u(&sBh[boff]));
            ldsm_x4(bl_[nt], s2u(&sBl[boff]));
        }
#pragma unroll
        for (int mt = 0; mt < 4; mt++) {
            uint32_t ah[2][4], al[2][4];
#pragma unroll
            for (int s = 0; s < 2; s++) {
                const int aoff = (wm * 64 + mt * 16 + (lane & 15)) * GSTR + s * 16 + (lane >> 4) * 8;
                ldsm_x4(ah[s], s2u(&sAh[aoff]));
                ldsm_x4(al[s], s2u(&sAl[aoff]));
            }
#pragma unroll
            for (int s = 0; s < 2; s++)
#pragma unroll
                for (int nt = 0; nt < 4; nt++) {
                    mma16816(acc[mt][nt], ah[s], &bh_[nt][2 * s]);
                    mma16816(acc[mt][nt], ah[s], &bl_[nt][2 * s]);
                    mma16816(acc[mt][nt], al[s], &bh_[nt][2 * s]);
                }
        }
        __syncthreads();
    }

    // Epilogue
#pragma unroll
    for (int mt = 0; mt < 4; mt++) {
#pragma unroll
        for (int nt = 0; nt < 4; nt++) {
            const int rA = bm + wm * 64 + mt * 16 + (lane >> 2);
            const int rB = rA + 8;
            const int o = bn + wn * 32 + nt * 8 + 2 * (lane & 3);
            if (MODE == 0) {
                const int part = o >> 9, h = (o >> 6) & 7, d = o & 63;
                const int bA = rA / NN, nA = rA - bA * NN;
                const int bB = rB / NN, nB = rB - bB * NN;
                const int bhA = bA * HH + h, bhB = bB * HH + h;
                __nv_bfloat16 h0, l0, h1, l1, h2, l2, h3, l3;
                split2(acc[mt][nt][0], h0, l0); split2(acc[mt][nt][1], h1, l1);
                split2(acc[mt][nt][2], h2, l2); split2(acc[mt][nt][3], h3, l3);
                if (part == 2) {
                    const size_t iA = ((size_t)bhA * DD + d) * NN + nA;
                    const size_t iB = ((size_t)bhB * DD + d) * NN + nB;
                    g_vth[iA] = h0; g_vtl[iA] = l0;
                    g_vth[iA + NN] = h1; g_vtl[iA + NN] = l1;
                    g_vth[iB] = h2; g_vtl[iB] = l2;
                    g_vth[iB + NN] = h3; g_vtl[iB + NN] = l3;
                } else {
                    __nv_bfloat16* dh = (part == 0) ? g_qh : g_kh;
                    __nv_bfloat16* dl = (part == 0) ? g_ql : g_kl;
                    const size_t iA = ((size_t)bhA * NN + nA) * DD + d;
                    const size_t iB = ((size_t)bhB * NN + nB) * DD + d;
                    *(uint32_t*)&dh[iA] = pack2(h0, h1);
                    *(uint32_t*)&dl[iA] = pack2(l0, l1);
                    *(uint32_t*)&dh[iB] = pack2(h2, h3);
                    *(uint32_t*)&dl[iB] = pack2(l2, l3);
                }
            } else {
                const float b0 = bias[o], b1 = bias[o + 1];
                *(float2*)&out[(size_t)rA * CC + o] =
                    make_float2(acc[mt][nt][0] + b0, acc[mt][nt][1] + b1);
                *(float2*)&out[(size_t)rB * CC + o] =
                    make_float2(acc[mt][nt][2] + b0, acc[mt][nt][3] + b1);
            }
        }
    }
}

// ---------------------------------------------------------------------------
// Flash attention. CTA = 128 queries x one (b,h), 8 warps, 64-key tiles,
// 2-stage cp.async pipeline. Locality bias from LUT (row-const dropped:
// softmax is shift-invariant per row).
// ---------------------------------------------------------------------------
constexpr int FSTR = 72;                // 144B rows
constexpr int F_TILE = 64 * FSTR;       // elems per array
constexpr int F_STAGE = 4 * F_TILE;     // Kh, Kl, Vh, Vl
constexpr int F_SMEM = 2 * F_STAGE * 2; // bytes = 73728

__global__ __launch_bounds__(256, 2)
void flash_mma(const float* __restrict__ temp, const float* __restrict__ lw) {
    extern __shared__ __nv_bfloat16 smem[];

    const int tid = threadIdx.x;
    const int lane = tid & 31, warp = tid >> 5;
    const int q0 = blockIdx.x * 128;
    const int bh = blockIdx.y;
    const int h = bh & 7, b = bh >> 3;

    const __nv_bfloat16* Qh = g_qh + (size_t)bh * NN * DD;
    const __nv_bfloat16* Ql = g_ql + (size_t)bh * NN * DD;
    const __nv_bfloat16* Kh = g_kh + (size_t)bh * NN * DD;
    const __nv_bfloat16* Kl = g_kl + (size_t)bh * NN * DD;
    const __nv_bfloat16* Vh = g_vth + (size_t)bh * NN * DD;  // [d][n]
    const __nv_bfloat16* Vl = g_vtl + (size_t)bh * NN * DD;

    const float scale = __expf(temp[h]);
    const float wb = lw[h] * (1.0f / 4418.0f);  // / (2*47^2)

    // ---- Stage Q (128x64 hi/lo) through smem, extract fragments ----
    {
        __nv_bfloat16* Qsh = smem;                 // 128*FSTR
        __nv_bfloat16* Qsl = smem + 128 * FSTR;
#pragma unroll
        for (int it = 0; it < 4; it++) {
            const int c = tid + 256 * it;          // 1024 chunks
            const int row = c >> 3, col = c & 7;
            const size_t g = (size_t)(q0 + row) * DD + col * 8;
            const int so = row * FSTR + col * 8;
            cpa16(s2u(&Qsh[so]), &Qh[g]);
            cpa16(s2u(&Qsl[so]), &Ql[g]);
        }
        CP_COMMIT();
        CP_WAIT0();
    }
    __syncthreads();

    uint32_t qfh[4][4], qfl[4][4];
    {
        const __nv_bfloat16* Qsh = smem;
        const __nv_bfloat16* Qsl = smem + 128 * FSTR;
#pragma unroll
        for (int s = 0; s < 4; s++) {
            const int off = (warp * 16 + (lane & 15)) * FSTR + s * 16 + (lane >> 4) * 8;
            ldsm_x4(qfh[s], s2u(&Qsh[off]));
            ldsm_x4(qfl[s], s2u(&Qsl[off]));
        }
    }
    __syncthreads();

    auto load_kv = [&](int s, int k0) {
        __nv_bfloat16* base = smem + s * F_STAGE;
#pragma unroll
        for (int it = 0; it < 2; it++) {
            const int c = tid + 256 * it;          // 512 chunks
            const int row = c >> 3, col = c & 7;
            const size_t gk = (size_t)(k0 + row) * DD + col * 8;
            const size_t gv = (size_t)row * NN + k0 + col * 8;
            const int so = row * FSTR + col * 8;
            cpa16(s2u(base + so), &Kh[gk]);
            cpa16(s2u(base + F_TILE + so), &Kl[gk]);
            cpa16(s2u(base + 2 * F_TILE + so), &Vh[gv]);
            cpa16(s2u(base + 3 * F_TILE + so), &Vl[gv]);
        }
        CP_COMMIT();
    };

    float oacc[8][4];
#pragma unroll
    for (int u = 0; u < 8; u++)
#pragma unroll
        for (int r = 0; r < 4; r++) oacc[u][r] = 0.0f;
    float mA = -1e30f, mB = -1e30f, lA = 0.0f, lB = 0.0f;

    const int qA = q0 + warp * 16 + (lane >> 2), qB = qA + 8;
    const float4 qlocA = g_loc[qA], qlocB = g_loc[qB];
    const float byA = 2.0f * wb * qlocA.x, bxA = 2.0f * wb * qlocA.y;
    const float byB = 2.0f * wb * qlocB.x, bxB = 2.0f * wb * qlocB.y;

    constexpr int NKT = NN / 64;  // 36
    load_kv(0, 0);
    for (int kt = 0; kt < NKT; kt++) {
        if (kt + 1 < NKT) { load_kv((kt + 1) & 1, (kt + 1) * 64); CP_WAIT1(); }
        else              { CP_WAIT0(); }
        __syncthreads();
        const __nv_bfloat16* sKh = smem + (kt & 1) * F_STAGE;
        const __nv_bfloat16* sKl = sKh + F_TILE;
        const __nv_bfloat16* sVh = sKh + 2 * F_TILE;
        const __nv_bfloat16* sVl = sKh + 3 * F_TILE;
        const int k0 = kt * 64;

        // S = Q @ K^T  (16 x 64 per warp)
        float sfr[8][4];
#pragma unroll
        for (int t = 0; t < 8; t++)
#pragma unroll
            for (int r = 0; r < 4; r++) sfr[t][r] = 0.0f;
#pragma unroll
        for (int t = 0; t < 8; t++) {
            const int base = (8 * t + (lane & 7)) * FSTR + (lane >> 3) * 8;
            uint32_t k0h[4], k1h[4], k0l[4], k1l[4];
            ldsm_x4(k0h, s2u(&sKh[base]));
            ldsm_x4(k1h, s2u(&sKh[base + 32]));
            ldsm_x4(k0l, s2u(&sKl[base]));
            ldsm_x4(k1l, s2u(&sKl[base + 32]));
            mma16816(sfr[t], qfh[0], &k0h[0]); mma16816(sfr[t], qfh[0], &k0l[0]); mma16816(sfr[t], qfl[0], &k0h[0]);
            mma16816(sfr[t], qfh[1], &k0h[2]); mma16816(sfr[t], qfh[1], &k0l[2]); mma16816(sfr[t], qfl[1], &k0h[2]);
            mma16816(sfr[t], qfh[2], &k1h[0]); mma16816(sfr[t], qfh[2], &k1l[0]); mma16816(sfr[t], qfl[2], &k1h[0]);
            mma16816(sfr[t], qfh[3], &k1h[2]); mma16816(sfr[t], qfh[3], &k1l[2]); mma16816(sfr[t], qfl[3], &k1h[2]);
        }

        // scale + locality bias (LUT) + row max
        float tmA = -1e30f, tmB = -1e30f;
#pragma unroll
        for (int t = 0; t < 8; t++) {
#pragma unroll
            for (int j = 0; j < 2; j++) {
                const int k = k0 + 8 * t + 2 * (lane & 3) + j;
                const float4 kl = __ldg(&g_loc[k]);
                const float cA = fmaf(byA, kl.x, fmaf(bxA, kl.y, -wb * kl.z));
                const float cB = fmaf(byB, kl.x, fmaf(bxB, kl.y, -wb * kl.z));
                sfr[t][j]     = fmaf(sfr[t][j],     scale, cA);
                sfr[t][2 + j] = fmaf(sfr[t][2 + j], scale, cB);
                tmA = fmaxf(tmA, sfr[t][j]);
                tmB = fmaxf(tmB, sfr[t][2 + j]);
            }
        }
        tmA = fmaxf(tmA, __shfl_xor_sync(0xffffffffu, tmA, 1));
        tmA = fmaxf(tmA, __shfl_xor_sync(0xffffffffu, tmA, 2));
        tmB = fmaxf(tmB, __shfl_xor_sync(0xffffffffu, tmB, 1));
        tmB = fmaxf(tmB, __shfl_xor_sync(0xffffffffu, tmB, 2));
        const float mnA = fmaxf(mA, tmA), mnB = fmaxf(mB, tmB);
        const float facA = __expf(mA - mnA), facB = __expf(mB - mnB);
        mA = mnA; mB = mnB;

        // exp + pack P fragments (A-frag layout) in registers
        uint32_t ah[4][4], al[4][4];
        float rsA = 0.0f, rsB = 0.0f;
#pragma unroll
        for (int s = 0; s < 4; s++) {
            const float p0 = __expf(sfr[2 * s][0] - mnA);
            const float p1 = __expf(sfr[2 * s][1] - mnA);
            const float p2 = __expf(sfr[2 * s][2] - mnB);
            const float p3 = __expf(sfr[2 * s][3] - mnB);
            const float r0 = __expf(sfr[2 * s + 1][0] - mnA);
            const float r1 = __expf(sfr[2 * s + 1][1] - mnA);
            const float r2 = __expf(sfr[2 * s + 1][2] - mnB);
            const float r3 = __expf(sfr[2 * s + 1][3] - mnB);
            rsA += p0 + p1 + r0 + r1;
            rsB += p2 + p3 + r2 + r3;
            __nv_bfloat16 h0, l0, h1, l1;
            split2(p0, h0, l0); split2(p1, h1, l1);
            ah[s][0] = pack2(h0, h1); al[s][0] = pack2(l0, l1);
            split2(p2, h0, l0); split2(p3, h1, l1);
            ah[s][1] = pack2(h0, h1); al[s][1] = pack2(l0, l1);
            split2(r0, h0, l0); split2(r1, h1, l1);
            ah[s][2] = pack2(h0, h1); al[s][2] = pack2(l0, l1);
            split2(r2, h0, l0); split2(r3, h1, l1);
            ah[s][3] = pack2(h0, h1); al[s][3] = pack2(l0, l1);
        }
        rsA += __shfl_xor_sync(0xffffffffu, rsA, 1);
        rsA += __shfl_xor_sync(0xffffffffu, rsA, 2);
        rsB += __shfl_xor_sync(0xffffffffu, rsB, 1);
        rsB += __shfl_xor_sync(0xffffffffu, rsB, 2);
        lA = lA * facA + rsA;
        lB = lB * facB + rsB;
#pragma unroll
        for (int u = 0; u < 8; u++) {
            oacc[u][0] *= facA; oacc[u][1] *= facA;
            oacc[u][2] *= facB; oacc[u][3] *= facB;
        }

        // O += P @ V
#pragma unroll
        for (int u = 0; u < 8; u++) {
            const int base = (8 * u + (lane & 7)) * FSTR + (lane >> 3) * 8;
            uint32_t v0h[4], v1h[4], v0l[4], v1l[4];
            ldsm_x4(v0h, s2u(&sVh[base]));
            ldsm_x4(v1h, s2u(&sVh[base + 32]));
            ldsm_x4(v0l, s2u(&sVl[base]));
            ldsm_x4(v1l, s2u(&sVl[base + 32]));
            mma16816(oacc[u], ah[0], &v0h[0]); mma16816(oacc[u], ah[0], &v0l[0]); mma16816(oacc[u], al[0], &v0h[0]);
            mma16816(oacc[u], ah[1], &v0h[2]); mma16816(oacc[u], ah[1], &v0l[2]); mma16816(oacc[u], al[1], &v0h[2]);
            mma16816(oacc[u], ah[2], &v1h[0]); mma16816(oacc[u], ah[2], &v1l[0]); mma16816(oacc[u], al[2], &v1h[0]);
            mma16816(oacc[u], ah[3], &v1h[2]); mma16816(oacc[u], ah[3], &v1l[2]); mma16816(oacc[u], al[3], &v1h[2]);
        }
        __syncthreads();
    }

    // epilogue: normalize, split, write att bf16 hi/lo [b][n][C]
    const float invA = 1.0f / lA, invB = 1.0f / lB;
    const size_t baseA = ((size_t)(b * NN + qA)) * CC + h * DD;
    const size_t baseB = ((size_t)(b * NN + qB)) * CC + h * DD;
#pragma unroll
    for (int u = 0; u < 8; u++) {
        const int c = 8 * u + 2 * (lane & 3);
        __nv_bfloat16 h0, l0, h1, l1;
        split2(oacc[u][0] * invA, h0, l0); split2(oacc[u][1] * invA, h1, l1);
        *(uint32_t*)&g_ath[baseA + c] = pack2(h0, h1);
        *(uint32_t*)&g_atl[baseA + c] = pack2(l0, l1);
        split2(oacc[u][2] * invB, h0, l0); split2(oacc[u][3] * invB, h1, l1);
        *(uint32_t*)&g_ath[baseB + c] = pack2(h0, h1);
        *(uint32_t*)&g_atl[baseB + c] = pack2(l0, l1);
    }
}

// ---------------------------------------------------------------------------
extern "C" void kernel_launch(void* const* d_in, const int* in_sizes, int n_in,
                              void* d_out, int out_size) {
    const float* x      = (const float*)d_in[0];
    const float* qkv_w  = (const float*)d_in[1];
    const float* proj_w = (const float*)d_in[2];
    const float* proj_b = (const float*)d_in[3];
    const float* temp   = (const float*)d_in[4];
    const float* lw     = (const float*)d_in[5];
    float* out = (float*)d_out;

    cudaFuncSetAttribute(mma_gemm<0>, cudaFuncAttributeMaxDynamicSharedMemorySize, G_SMEM);
    cudaFuncSetAttribute(mma_gemm<1>, cudaFuncAttributeMaxDynamicSharedMemorySize, G_SMEM);
    cudaFuncSetAttribute(flash_mma,   cudaFuncAttributeMaxDynamicSharedMemorySize, F_SMEM);

    const int prep_blocks = (int)((SX + SQW + SPW) / 4 / 256);  // 10240
    prep_split<<<prep_blocks, 256>>>(x, qkv_w, proj_w);

    mma_gemm<0><<<dim3(M_TOT / 128, 1536 / 128), 256, G_SMEM>>>(nullptr, nullptr);

    flash_mma<<<dim3(NN / 128, BB * HH), 256, F_SMEM>>>(temp, lw);

    mma_gemm<1><<<dim3(M_TOT / 128, CC / 128), 256, G_SMEM>>>(proj_b, out);
}